// round 4
// baseline (speedup 1.0000x reference)
#include <cuda_runtime.h>
#include <cuda_fp16.h>
#include <cstdint>

#define NNODES 100000
#define EMAX   1600000
#define NGRAPH 64
#define NBLOCKS 592     // 148 SMs x 4 blocks (co-resident; GB300 has 152 SMs)
#define NTHREADS 256

// ---------------- device scratch ----------------
__device__ int    g_cnt[NNODES];
__device__ int    g_rowstart[NNODES];
__device__ int    g_cursor[NNODES];
__device__ int    g_blocksum[128];
__device__ int    g_csrsrc[EMAX];
__device__ float  g_dis[NNODES];
__device__ __half g_hs1h[NNODES * 32];
__device__ __half2 g_hs2h[NNODES * 32];
__device__ int    g_pool[NGRAPH * 64];

// software grid barrier state
__device__ int          g_bar_cnt = 0;
__device__ volatile int g_bar_gen = 0;

// ---------------- helpers ----------------
__device__ __forceinline__ int fenc(float v) {
    int i = __float_as_int(v);
    return i >= 0 ? i : (i ^ 0x7FFFFFFF);
}
__device__ __forceinline__ float fdec(int i) {
    return __int_as_float(i >= 0 ? i : (i ^ 0x7FFFFFFF));
}
__device__ __forceinline__ float lrelu(float v) { return v > 0.0f ? v : 0.1f * v; }

#define ENC_NEG_INF ((int)0x807FFFFF)
#define FNEG_INF    __int_as_float(0xFF800000)

__device__ __forceinline__ void grid_sync() {
    __syncthreads();
    if (threadIdx.x == 0) {
        int gen = g_bar_gen;
        __threadfence();
        if (atomicAdd(&g_bar_cnt, 1) == NBLOCKS - 1) {
            g_bar_cnt = 0;
            __threadfence();
            g_bar_gen = gen + 1;
        } else {
            while (g_bar_gen == gen) { __nanosleep(64); }
        }
        __threadfence();
    }
    __syncthreads();
}

union SmemU {
    float w[128 * 32];                                 // W1 (16KB) / W2 (first 8KB)
    struct { int sT[256]; int s128[128]; } scan;
    struct { float2 sv[8][32]; int sb[8]; } pool;
};

// ================= fused persistent kernel =================
__global__ void __launch_bounds__(NTHREADS, 4)
k_fused(const float* __restrict__ x, const int* __restrict__ src,
        const int* __restrict__ dst, const int* __restrict__ batch,
        const float* __restrict__ W1, const float* __restrict__ b1,
        const float* __restrict__ W2, const float* __restrict__ b2,
        int Nn, int E, int NB) {
    __shared__ SmemU smem;

    const int tid   = threadIdx.x;
    const int gtid  = blockIdx.x * NTHREADS + tid;
    const int nthr  = NBLOCKS * NTHREADS;
    const int lane  = tid & 31;
    const int gwarp = gtid >> 5;
    const int nwarp = nthr >> 5;

    // ---- P0: zero counters + pool init ----
    for (int i = gtid; i < Nn; i += nthr) g_cnt[i] = 0;
    for (int i = gtid; i < NGRAPH * 64; i += nthr) g_pool[i] = ENC_NEG_INF;
    grid_sync();

    // ---- P1: degree histogram ----
    {
        int e4 = E >> 2;
        const int4* d4 = reinterpret_cast<const int4*>(dst);
        for (int t = gtid; t < e4; t += nthr) {
            int4 d = d4[t];
            atomicAdd(&g_cnt[d.x], 1);
            atomicAdd(&g_cnt[d.y], 1);
            atomicAdd(&g_cnt[d.z], 1);
            atomicAdd(&g_cnt[d.w], 1);
        }
        for (int e = e4 * 4 + gtid; e < E; e += nthr) atomicAdd(&g_cnt[dst[e]], 1);
    }
    grid_sync();

    // ---- P2: dis + per-chunk scan (blocks < NB each scan 1024 counts) ----
    for (int n = gtid; n < Nn; n += nthr) g_dis[n] = rsqrtf((float)g_cnt[n] + 1.0f);
    if (blockIdx.x < NB) {
        int base = blockIdx.x * 1024 + tid * 4;
        int v0 = (base + 0 < Nn) ? g_cnt[base + 0] : 0;
        int v1 = (base + 1 < Nn) ? g_cnt[base + 1] : 0;
        int v2 = (base + 2 < Nn) ? g_cnt[base + 2] : 0;
        int v3 = (base + 3 < Nn) ? g_cnt[base + 3] : 0;
        int tot = v0 + v1 + v2 + v3;
        smem.scan.sT[tid] = tot;
        __syncthreads();
        for (int off = 1; off < 256; off <<= 1) {
            int xv = 0;
            if (tid >= off) xv = smem.scan.sT[tid - off];
            __syncthreads();
            if (tid >= off) smem.scan.sT[tid] += xv;
            __syncthreads();
        }
        int run = smem.scan.sT[tid] - tot;
        if (base + 0 < Nn) g_rowstart[base + 0] = run; run += v0;
        if (base + 1 < Nn) g_rowstart[base + 1] = run; run += v1;
        if (base + 2 < Nn) g_rowstart[base + 2] = run; run += v2;
        if (base + 3 < Nn) g_rowstart[base + 3] = run;
        if (tid == 255) g_blocksum[blockIdx.x] = smem.scan.sT[255];
    }
    grid_sync();

    // ---- P3: every block redundantly scans block sums, then applies offsets ----
    if (tid < 128) smem.scan.s128[tid] = (tid < NB) ? g_blocksum[tid] : 0;
    __syncthreads();
    for (int off = 1; off < 128; off <<= 1) {
        int xv = 0;
        if (tid >= off && tid < 128) xv = smem.scan.s128[tid - off];
        __syncthreads();
        if (tid >= off && tid < 128) smem.scan.s128[tid] += xv;
        __syncthreads();
    }
    for (int n = gtid; n < Nn; n += nthr) {
        int bn = n >> 10;
        int off = (bn == 0) ? 0 : smem.scan.s128[bn - 1];
        int rs = g_rowstart[n] + off;
        g_rowstart[n] = rs;
        g_cursor[n] = rs;
    }
    grid_sync();

    // ---- P4: CSR fill + gemm1 (merged phase, no barrier between) ----
    for (int i = tid; i < 128 * 32; i += NTHREADS) smem.w[i] = W1[i];
    __syncthreads();
    {
        int e4 = E >> 2;
        const int4* d4 = reinterpret_cast<const int4*>(dst);
        const int4* s4 = reinterpret_cast<const int4*>(src);
        for (int t = gtid; t < e4; t += nthr) {
            int4 d = d4[t];
            int4 sc = s4[t];
            g_csrsrc[atomicAdd(&g_cursor[d.x], 1)] = sc.x;
            g_csrsrc[atomicAdd(&g_cursor[d.y], 1)] = sc.y;
            g_csrsrc[atomicAdd(&g_cursor[d.z], 1)] = sc.z;
            g_csrsrc[atomicAdd(&g_cursor[d.w], 1)] = sc.w;
        }
        for (int e = e4 * 4 + gtid; e < E; e += nthr)
            g_csrsrc[atomicAdd(&g_cursor[dst[e]], 1)] = src[e];
    }
    // gemm1: hs1 = fp16(dis * (x @ W1)), warp-stride over nodes
    for (int node = gwarp; node < Nn; node += nwarp) {
        const float* xr = x + (size_t)node * 128;
        float acc = 0.0f;
#pragma unroll
        for (int kt = 0; kt < 4; kt++) {
            float xk = xr[kt * 32 + lane];
#pragma unroll
            for (int kk = 0; kk < 32; kk++) {
                float xv = __shfl_sync(0xFFFFFFFFu, xk, kk);
                acc = fmaf(xv, smem.w[(kt * 32 + kk) * 32 + lane], acc);
            }
        }
        g_hs1h[(size_t)node * 32 + lane] = __float2half_rn(g_dis[node] * acc);
    }
    grid_sync();

    // ---- P5: agg1 + lrelu + GEMM2 -> g_hs2h ----
    for (int i = tid; i < 32 * 64; i += NTHREADS) smem.w[i] = W2[i];
    __syncthreads();
    {
        float b1l = b1[lane];
        const float2* sWp = reinterpret_cast<const float2*>(smem.w);
        for (int node = gwarp; node < Nn; node += nwarp) {
            int rs = g_rowstart[node];
            int cnt = g_cnt[node];
            float a0 = 0.f, a1 = 0.f, a2 = 0.f, a3 = 0.f;
            for (int base = 0; base < cnt; base += 32) {
                int rem = cnt - base;
                int m = rem < 32 ? rem : 32;
                int sidx = 0;
                if (lane < m) sidx = g_csrsrc[rs + base + lane];
                int k = 0;
                for (; k + 4 <= m; k += 4) {
                    int s0 = __shfl_sync(0xFFFFFFFFu, sidx, k);
                    int s1 = __shfl_sync(0xFFFFFFFFu, sidx, k + 1);
                    int s2 = __shfl_sync(0xFFFFFFFFu, sidx, k + 2);
                    int s3 = __shfl_sync(0xFFFFFFFFu, sidx, k + 3);
                    a0 += __half2float(__ldg(&g_hs1h[(size_t)s0 * 32 + lane]));
                    a1 += __half2float(__ldg(&g_hs1h[(size_t)s1 * 32 + lane]));
                    a2 += __half2float(__ldg(&g_hs1h[(size_t)s2 * 32 + lane]));
                    a3 += __half2float(__ldg(&g_hs1h[(size_t)s3 * 32 + lane]));
                }
                for (; k < m; k++) {
                    int s = __shfl_sync(0xFFFFFFFFu, sidx, k);
                    a0 += __half2float(__ldg(&g_hs1h[(size_t)s * 32 + lane]));
                }
            }
            float d = g_dis[node];
            float acc = (a0 + a1) + (a2 + a3);
            float self = __half2float(g_hs1h[(size_t)node * 32 + lane]);
            float v = lrelu(d * (acc + self) + b1l);

            float o0 = 0.f, o1 = 0.f;
#pragma unroll
            for (int kk = 0; kk < 32; kk++) {
                float xv = __shfl_sync(0xFFFFFFFFu, v, kk);
                float2 w = sWp[kk * 32 + lane];
                o0 = fmaf(xv, w.x, o0);
                o1 = fmaf(xv, w.y, o1);
            }
            g_hs2h[(size_t)node * 32 + lane] = __floats2half2_rn(d * o0, d * o1);
        }
    }
    grid_sync();

    // ---- P6: agg2 + bias + fused max pool (batch sorted) ----
    {
        int wid = tid >> 5;
        float2 bb = reinterpret_cast<const float2*>(b2)[lane];
        int ngrp = (Nn + 7) / 8;
        for (int grp = blockIdx.x; grp < ngrp; grp += NBLOCKS) {
            int node = grp * 8 + wid;
            bool valid = node < Nn;
            if (lane == 0) smem.pool.sb[wid] = valid ? batch[node] : -1;
            if (valid) {
                int rs = g_rowstart[node];
                int cnt = g_cnt[node];
                float ax0 = 0.f, ay0 = 0.f, ax1 = 0.f, ay1 = 0.f;
                float ax2 = 0.f, ay2 = 0.f, ax3 = 0.f, ay3 = 0.f;
                for (int base = 0; base < cnt; base += 32) {
                    int rem = cnt - base;
                    int m = rem < 32 ? rem : 32;
                    int sidx = 0;
                    if (lane < m) sidx = g_csrsrc[rs + base + lane];
                    int k = 0;
                    for (; k + 4 <= m; k += 4) {
                        int s0 = __shfl_sync(0xFFFFFFFFu, sidx, k);
                        int s1 = __shfl_sync(0xFFFFFFFFu, sidx, k + 1);
                        int s2 = __shfl_sync(0xFFFFFFFFu, sidx, k + 2);
                        int s3 = __shfl_sync(0xFFFFFFFFu, sidx, k + 3);
                        float2 v0 = __half22float2(__ldg(&g_hs2h[(size_t)s0 * 32 + lane]));
                        float2 v1 = __half22float2(__ldg(&g_hs2h[(size_t)s1 * 32 + lane]));
                        float2 v2 = __half22float2(__ldg(&g_hs2h[(size_t)s2 * 32 + lane]));
                        float2 v3 = __half22float2(__ldg(&g_hs2h[(size_t)s3 * 32 + lane]));
                        ax0 += v0.x; ay0 += v0.y;
                        ax1 += v1.x; ay1 += v1.y;
                        ax2 += v2.x; ay2 += v2.y;
                        ax3 += v3.x; ay3 += v3.y;
                    }
                    for (; k < m; k++) {
                        int s = __shfl_sync(0xFFFFFFFFu, sidx, k);
                        float2 v = __half22float2(__ldg(&g_hs2h[(size_t)s * 32 + lane]));
                        ax0 += v.x; ay0 += v.y;
                    }
                }
                float2 self = __half22float2(g_hs2h[(size_t)node * 32 + lane]);
                float d = g_dis[node];
                float2 o;
                o.x = d * ((ax0 + ax1) + (ax2 + ax3) + self.x) + bb.x;
                o.y = d * ((ay0 + ay1) + (ay2 + ay3) + self.y) + bb.y;
                smem.pool.sv[wid][lane] = o;
            }
            __syncthreads();
            if (tid < 64) {
                int f = tid;
                int half_ = f >> 1;
                int comp = f & 1;
                int curg = -1;
                float mx = FNEG_INF;
                for (int w = 0; w < 8; w++) {
                    int bg = smem.pool.sb[w];
                    if (bg < 0) continue;
                    float2 p = smem.pool.sv[w][half_];
                    float val = comp ? p.y : p.x;
                    if (bg != curg) {
                        if (curg >= 0) atomicMax(&g_pool[curg * 64 + f], fenc(mx));
                        curg = bg;
                        mx = FNEG_INF;
                    }
                    mx = fmaxf(mx, val);
                }
                if (curg >= 0) atomicMax(&g_pool[curg * 64 + f], fenc(mx));
            }
            __syncthreads();
        }
    }
}

// ================= MLP head =================
__global__ void k_mlp(const float* __restrict__ Wl1, const float* __restrict__ bl1,
                      const float* __restrict__ Wl2, const float* __restrict__ bl2,
                      const float* __restrict__ Wl3, const float* __restrict__ bl3,
                      float* __restrict__ out) {
    __shared__ float sg[64 * 64];
    __shared__ float st1[64 * 128];
    __shared__ float st2[64 * 64];
    int t = threadIdx.x;
    for (int i = t; i < 64 * 64; i += blockDim.x) sg[i] = fdec(g_pool[i]);
    __syncthreads();
    for (int idx = t; idx < 64 * 128; idx += blockDim.x) {
        int i = idx >> 7, j = idx & 127;
        float s = bl1[j];
        for (int k = 0; k < 64; k++) s = fmaf(sg[i * 64 + k], Wl1[k * 128 + j], s);
        st1[idx] = lrelu(s);
    }
    __syncthreads();
    for (int idx = t; idx < 64 * 64; idx += blockDim.x) {
        int i = idx >> 6, j = idx & 63;
        float s = bl2[j];
        for (int k = 0; k < 128; k++) s = fmaf(st1[i * 128 + k], Wl2[k * 64 + j], s);
        st2[idx] = lrelu(s);
    }
    __syncthreads();
    if (t < 64) {
        float s = bl3[0];
        for (int k = 0; k < 64; k++) s = fmaf(st2[t * 64 + k], Wl3[k], s);
        out[t] = s;
    }
}

// ---------------- launch ----------------
extern "C" void kernel_launch(void* const* d_in, const int* in_sizes, int n_in,
                              void* d_out, int out_size) {
    const float* x   = (const float*)d_in[0];
    const int*   ei  = (const int*)d_in[1];
    const int*   bat = (const int*)d_in[2];
    const float* W1  = (const float*)d_in[3];
    const float* b1  = (const float*)d_in[4];
    const float* W2  = (const float*)d_in[5];
    const float* b2  = (const float*)d_in[6];
    const float* Wl1 = (const float*)d_in[7];
    const float* bl1 = (const float*)d_in[8];
    const float* Wl2 = (const float*)d_in[9];
    const float* bl2 = (const float*)d_in[10];
    const float* Wl3 = (const float*)d_in[11];
    const float* bl3 = (const float*)d_in[12];
    float* out = (float*)d_out;

    int Nn = in_sizes[0] / 128;
    int E  = in_sizes[1] / 2;
    const int* src = ei;
    const int* dst = ei + E;
    int NB = (Nn + 1023) / 1024;

    k_fused<<<NBLOCKS, NTHREADS>>>(x, src, dst, bat, W1, b1, W2, b2, Nn, E, NB);
    k_mlp<<<1, 128>>>(Wl1, bl1, Wl2, bl2, Wl3, bl3, out);
}

// round 5
// speedup vs baseline: 1.3261x; 1.3261x over previous
#include <cuda_runtime.h>
#include <cuda_fp16.h>
#include <cstdint>

#define NNODES 100000
#define EMAX   1600000
#define NGRAPH 64

// ---------------- device scratch ----------------
__device__ int    g_cnt[NNODES];
__device__ int    g_rowstart[NNODES];
__device__ int    g_cursor[NNODES];
__device__ int    g_blocksum[128];
__device__ int    g_csrsrc[EMAX];
__device__ float  g_dis[NNODES];
__device__ __half g_hs1h[NNODES * 32];    // fp16: dis * (x @ W1)
__device__ __half2 g_hs2h[NNODES * 32];   // fp16x2: dis * (lrelu(layer1) @ W2)
__device__ int    g_pool[NGRAPH * 64];    // order-preserving-encoded float max

// ---------------- helpers ----------------
__device__ __forceinline__ int fenc(float v) {
    int i = __float_as_int(v);
    return i >= 0 ? i : (i ^ 0x7FFFFFFF);
}
__device__ __forceinline__ float fdec(int i) {
    return __int_as_float(i >= 0 ? i : (i ^ 0x7FFFFFFF));
}
__device__ __forceinline__ float lrelu(float v) { return v > 0.0f ? v : 0.1f * v; }

#define ENC_NEG_INF ((int)0x807FFFFF)
#define FNEG_INF    __int_as_float(0xFF800000)

// ---------------- kernels ----------------

// histogram of dst (int4-vectorized)
__global__ void k_count(const int* __restrict__ dst, int E) {
    int t = blockIdx.x * blockDim.x + threadIdx.x;
    int e4 = E >> 2;
    if (t < e4) {
        int4 d = reinterpret_cast<const int4*>(dst)[t];
        atomicAdd(&g_cnt[d.x], 1);
        atomicAdd(&g_cnt[d.y], 1);
        atomicAdd(&g_cnt[d.z], 1);
        atomicAdd(&g_cnt[d.w], 1);
    } else {
        int e = e4 * 4 + (t - e4);
        if (e < E) atomicAdd(&g_cnt[dst[e]], 1);
    }
}

// dis = rsqrt(deg+1)  + pool init (early, so gemm1 can fork right after)
__global__ void k_dis(int Nn) {
    int n = blockIdx.x * blockDim.x + threadIdx.x;
    if (n < Nn) g_dis[n] = rsqrtf((float)g_cnt[n] + 1.0f);
    if (n < NGRAPH * 64) g_pool[n] = ENC_NEG_INF;
}

// per-block (1024 elems) exclusive scan of g_cnt -> g_rowstart, block totals -> g_blocksum
__global__ void k_scan1(int Nn) {
    __shared__ int sT[256];
    int t = threadIdx.x;
    int base = blockIdx.x * 1024 + t * 4;
    int v0 = (base + 0 < Nn) ? g_cnt[base + 0] : 0;
    int v1 = (base + 1 < Nn) ? g_cnt[base + 1] : 0;
    int v2 = (base + 2 < Nn) ? g_cnt[base + 2] : 0;
    int v3 = (base + 3 < Nn) ? g_cnt[base + 3] : 0;
    int tot = v0 + v1 + v2 + v3;
    sT[t] = tot;
    __syncthreads();
    for (int off = 1; off < 256; off <<= 1) {
        int x = 0;
        if (t >= off) x = sT[t - off];
        __syncthreads();
        if (t >= off) sT[t] += x;
        __syncthreads();
    }
    int run = sT[t] - tot;
    if (base + 0 < Nn) g_rowstart[base + 0] = run; run += v0;
    if (base + 1 < Nn) g_rowstart[base + 1] = run; run += v1;
    if (base + 2 < Nn) g_rowstart[base + 2] = run; run += v2;
    if (base + 3 < Nn) g_rowstart[base + 3] = run;
    if (t == 255) g_blocksum[blockIdx.x] = sT[255];
}

// add block offsets (recompute 128-entry scan per block), init cursors
__global__ void k_scan3(int Nn, int NB) {
    __shared__ int s[128];
    int t = threadIdx.x;
    if (t < 128) s[t] = (t < NB) ? g_blocksum[t] : 0;
    __syncthreads();
    for (int off = 1; off < 128; off <<= 1) {
        int x = 0;
        if (t >= off && t < 128) x = s[t - off];
        __syncthreads();
        if (t >= off && t < 128) s[t] += x;
        __syncthreads();
    }
    int n = blockIdx.x * blockDim.x + t;
    if (n >= Nn) return;
    int bn = n >> 10;
    int off = (bn == 0) ? 0 : s[bn - 1];
    int rs = g_rowstart[n] + off;
    g_rowstart[n] = rs;
    g_cursor[n] = rs;
}

// scatter src ids into CSR (int4-vectorized)
__global__ void k_fill(const int* __restrict__ src, const int* __restrict__ dst, int E) {
    int t = blockIdx.x * blockDim.x + threadIdx.x;
    int e4 = E >> 2;
    if (t < e4) {
        int4 d = reinterpret_cast<const int4*>(dst)[t];
        int4 sc = reinterpret_cast<const int4*>(src)[t];
        g_csrsrc[atomicAdd(&g_cursor[d.x], 1)] = sc.x;
        g_csrsrc[atomicAdd(&g_cursor[d.y], 1)] = sc.y;
        g_csrsrc[atomicAdd(&g_cursor[d.z], 1)] = sc.z;
        g_csrsrc[atomicAdd(&g_cursor[d.w], 1)] = sc.w;
    } else {
        int e = e4 * 4 + (t - e4);
        if (e < E) g_csrsrc[atomicAdd(&g_cursor[dst[e]], 1)] = src[e];
    }
}

// hs1 = fp16( dis * (x @ W1) )
__global__ void k_gemm1(const float* __restrict__ x, const float* __restrict__ W1, int Nn) {
    __shared__ float sW[128 * 32];
    for (int i = threadIdx.x; i < 128 * 32; i += blockDim.x) sW[i] = W1[i];
    __syncthreads();
    int warp = (blockIdx.x * blockDim.x + threadIdx.x) >> 5;
    int lane = threadIdx.x & 31;
    if (warp >= Nn) return;
    const float* xr = x + (size_t)warp * 128;
    float acc = 0.0f;
#pragma unroll
    for (int kt = 0; kt < 4; kt++) {
        float xk = xr[kt * 32 + lane];
#pragma unroll
        for (int kk = 0; kk < 32; kk++) {
            float xv = __shfl_sync(0xFFFFFFFFu, xk, kk);
            acc = fmaf(xv, sW[(kt * 32 + kk) * 32 + lane], acc);
        }
    }
    g_hs1h[(size_t)warp * 32 + lane] = __float2half_rn(g_dis[warp] * acc);
}

// layer-1 aggregation + lrelu + GEMM2, writes g_hs2h (half2)
__global__ void k_agg1(const float* __restrict__ b1, const float* __restrict__ W2, int Nn) {
    __shared__ float sW[32 * 64];
    for (int i = threadIdx.x; i < 32 * 64; i += blockDim.x) sW[i] = W2[i];
    __syncthreads();
    int warp = (blockIdx.x * blockDim.x + threadIdx.x) >> 5;
    int lane = threadIdx.x & 31;
    if (warp >= Nn) return;

    int rs = g_rowstart[warp];
    int cnt = g_cnt[warp];
    float a0 = 0.f, a1 = 0.f, a2 = 0.f, a3 = 0.f;
    for (int base = 0; base < cnt; base += 32) {
        int rem = cnt - base;
        int m = rem < 32 ? rem : 32;
        int sidx = 0;
        if (lane < m) sidx = g_csrsrc[rs + base + lane];
        int k = 0;
        for (; k + 4 <= m; k += 4) {
            int s0 = __shfl_sync(0xFFFFFFFFu, sidx, k);
            int s1 = __shfl_sync(0xFFFFFFFFu, sidx, k + 1);
            int s2 = __shfl_sync(0xFFFFFFFFu, sidx, k + 2);
            int s3 = __shfl_sync(0xFFFFFFFFu, sidx, k + 3);
            a0 += __half2float(__ldg(&g_hs1h[(size_t)s0 * 32 + lane]));
            a1 += __half2float(__ldg(&g_hs1h[(size_t)s1 * 32 + lane]));
            a2 += __half2float(__ldg(&g_hs1h[(size_t)s2 * 32 + lane]));
            a3 += __half2float(__ldg(&g_hs1h[(size_t)s3 * 32 + lane]));
        }
        for (; k < m; k++) {
            int s = __shfl_sync(0xFFFFFFFFu, sidx, k);
            a0 += __half2float(__ldg(&g_hs1h[(size_t)s * 32 + lane]));
        }
    }
    float d = g_dis[warp];
    float acc = (a0 + a1) + (a2 + a3);
    float self = __half2float(g_hs1h[(size_t)warp * 32 + lane]);
    float v = lrelu(d * (acc + self) + b1[lane]);

    // GEMM2 on registers: lane produces output feats (2*lane, 2*lane+1)
    const float2* sWp = reinterpret_cast<const float2*>(sW);
    float o0 = 0.f, o1 = 0.f;
#pragma unroll
    for (int kk = 0; kk < 32; kk++) {
        float xv = __shfl_sync(0xFFFFFFFFu, v, kk);
        float2 w = sWp[kk * 32 + lane];
        o0 = fmaf(xv, w.x, o0);
        o1 = fmaf(xv, w.y, o1);
    }
    g_hs2h[(size_t)warp * 32 + lane] = __floats2half2_rn(d * o0, d * o1);
}

// layer-2 aggregation + bias + fused global max pool (batch sorted)
__global__ void k_agg2(const float* __restrict__ b2, const int* __restrict__ batch, int Nn) {
    __shared__ float2 sv[8][32];
    __shared__ int sb[8];
    int wid = threadIdx.x >> 5;
    int lane = threadIdx.x & 31;
    int node = blockIdx.x * 8 + wid;
    bool valid = node < Nn;

    if (lane == 0) sb[wid] = valid ? batch[node] : -1;

    if (valid) {
        int rs = g_rowstart[node];
        int cnt = g_cnt[node];
        float ax0 = 0.f, ay0 = 0.f, ax1 = 0.f, ay1 = 0.f;
        float ax2 = 0.f, ay2 = 0.f, ax3 = 0.f, ay3 = 0.f;
        for (int base = 0; base < cnt; base += 32) {
            int rem = cnt - base;
            int m = rem < 32 ? rem : 32;
            int sidx = 0;
            if (lane < m) sidx = g_csrsrc[rs + base + lane];
            int k = 0;
            for (; k + 4 <= m; k += 4) {
                int s0 = __shfl_sync(0xFFFFFFFFu, sidx, k);
                int s1 = __shfl_sync(0xFFFFFFFFu, sidx, k + 1);
                int s2 = __shfl_sync(0xFFFFFFFFu, sidx, k + 2);
                int s3 = __shfl_sync(0xFFFFFFFFu, sidx, k + 3);
                float2 v0 = __half22float2(__ldg(&g_hs2h[(size_t)s0 * 32 + lane]));
                float2 v1 = __half22float2(__ldg(&g_hs2h[(size_t)s1 * 32 + lane]));
                float2 v2 = __half22float2(__ldg(&g_hs2h[(size_t)s2 * 32 + lane]));
                float2 v3 = __half22float2(__ldg(&g_hs2h[(size_t)s3 * 32 + lane]));
                ax0 += v0.x; ay0 += v0.y;
                ax1 += v1.x; ay1 += v1.y;
                ax2 += v2.x; ay2 += v2.y;
                ax3 += v3.x; ay3 += v3.y;
            }
            for (; k < m; k++) {
                int s = __shfl_sync(0xFFFFFFFFu, sidx, k);
                float2 v = __half22float2(__ldg(&g_hs2h[(size_t)s * 32 + lane]));
                ax0 += v.x; ay0 += v.y;
            }
        }
        float2 self = __half22float2(g_hs2h[(size_t)node * 32 + lane]);
        float2 bb = reinterpret_cast<const float2*>(b2)[lane];
        float d = g_dis[node];
        float2 o;
        o.x = d * ((ax0 + ax1) + (ax2 + ax3) + self.x) + bb.x;
        o.y = d * ((ay0 + ay1) + (ay2 + ay3) + self.y) + bb.y;
        sv[wid][lane] = o;
    }
    __syncthreads();

    if (threadIdx.x < 64) {
        int f = threadIdx.x;
        int half_ = f >> 1;
        int comp = f & 1;
        int curg = -1;
        float mx = FNEG_INF;
        for (int w = 0; w < 8; w++) {
            int bg = sb[w];
            if (bg < 0) continue;
            float2 p = sv[w][half_];
            float val = comp ? p.y : p.x;
            if (bg != curg) {
                if (curg >= 0) atomicMax(&g_pool[curg * 64 + f], fenc(mx));
                curg = bg;
                mx = FNEG_INF;
            }
            mx = fmaxf(mx, val);
        }
        if (curg >= 0) atomicMax(&g_pool[curg * 64 + f], fenc(mx));
    }
}

// MLP head, one block per graph (rows are independent): 64 -> 128 -> 64 -> 1
__global__ void k_mlp(const float* __restrict__ Wl1, const float* __restrict__ bl1,
                      const float* __restrict__ Wl2, const float* __restrict__ bl2,
                      const float* __restrict__ Wl3, const float* __restrict__ bl3,
                      float* __restrict__ out) {
    __shared__ float sg[64];     // pooled input row
    __shared__ float st1[128];   // layer-1 activations
    __shared__ float st2[64];    // layer-2 activations
    int g = blockIdx.x;
    int t = threadIdx.x;

    if (t < 64) sg[t] = fdec(g_pool[g * 64 + t]);
    __syncthreads();

    // layer 1: t1[j] = lrelu(bl1[j] + sum_k sg[k] * Wl1[k*128+j]);  j = t (128 threads)
    {
        float s = bl1[t];
#pragma unroll 8
        for (int k = 0; k < 64; k++) s = fmaf(sg[k], Wl1[k * 128 + t], s);
        st1[t] = lrelu(s);
    }
    __syncthreads();

    // layer 2: t2[j] = lrelu(bl2[j] + sum_k t1[k] * Wl2[k*64+j]);  j = t < 64
    if (t < 64) {
        float s = bl2[t];
#pragma unroll 8
        for (int k = 0; k < 128; k++) s = fmaf(st1[k], Wl2[k * 64 + t], s);
        st2[t] = lrelu(s);
    }
    __syncthreads();

    // layer 3: out[g] = bl3 + sum_k t2[k] * Wl3[k]  (2-warp reduce via smem)
    __shared__ float red[2];
    if (t < 64) {
        float p = st2[t] * Wl3[t];
#pragma unroll
        for (int off = 16; off > 0; off >>= 1)
            p += __shfl_down_sync(0xFFFFFFFFu, p, off);
        if ((t & 31) == 0) red[t >> 5] = p;
    }
    __syncthreads();
    if (t == 0) out[g] = red[0] + red[1] + bl3[0];
}

// ---------------- launch ----------------
extern "C" void kernel_launch(void* const* d_in, const int* in_sizes, int n_in,
                              void* d_out, int out_size) {
    const float* x   = (const float*)d_in[0];
    const int*   ei  = (const int*)d_in[1];
    const int*   bat = (const int*)d_in[2];
    const float* W1  = (const float*)d_in[3];
    const float* b1  = (const float*)d_in[4];
    const float* W2  = (const float*)d_in[5];
    const float* b2  = (const float*)d_in[6];
    const float* Wl1 = (const float*)d_in[7];
    const float* bl1 = (const float*)d_in[8];
    const float* Wl2 = (const float*)d_in[9];
    const float* bl2 = (const float*)d_in[10];
    const float* Wl3 = (const float*)d_in[11];
    const float* bl3 = (const float*)d_in[12];
    float* out = (float*)d_out;

    int Nn = in_sizes[0] / 128;
    int E  = in_sizes[1] / 2;
    const int* src = ei;
    const int* dst = ei + E;
    int NB = (Nn + 1023) / 1024;

    // one-time infra (host-side only; no device allocation)
    static cudaStream_t s2 = nullptr;
    static cudaEvent_t evFork = nullptr, evJoin = nullptr;
    static void* cntPtr = nullptr;
    if (s2 == nullptr) {
        cudaStreamCreateWithFlags(&s2, cudaStreamNonBlocking);
        cudaEventCreateWithFlags(&evFork, cudaEventDisableTiming);
        cudaEventCreateWithFlags(&evJoin, cudaEventDisableTiming);
        cudaGetSymbolAddress(&cntPtr, g_cnt);
    }

    cudaMemsetAsync(cntPtr, 0, NNODES * sizeof(int), 0);
    {
        int nThreads = (E >> 2) + (E & 3);
        k_count<<<(nThreads + 255) / 256, 256>>>(dst, E);
    }
    k_dis<<<(Nn + 255) / 256, 256>>>(Nn);

    // fork: gemm1 on s2 (needs only x, W1, dis)
    cudaEventRecord(evFork, 0);
    cudaStreamWaitEvent(s2, evFork, 0);
    k_gemm1<<<(Nn + 7) / 8, 256, 0, s2>>>(x, W1, Nn);
    cudaEventRecord(evJoin, s2);

    // main stream: CSR build
    k_scan1<<<NB, 256>>>(Nn);
    k_scan3<<<(Nn + 255) / 256, 256>>>(Nn, NB);
    {
        int nThreads = (E >> 2) + (E & 3);
        k_fill<<<(nThreads + 255) / 256, 256>>>(src, dst, E);
    }

    // join, then the serial tail
    cudaStreamWaitEvent(0, evJoin, 0);
    k_agg1<<<(Nn + 7) / 8, 256>>>(b1, W2, Nn);
    k_agg2<<<(Nn + 7) / 8, 256>>>(b2, bat, Nn);
    k_mlp<<<NGRAPH, 128>>>(Wl1, bl1, Wl2, bl2, Wl3, bl3, out);
}